// round 4
// baseline (speedup 1.0000x reference)
#include <cuda_runtime.h>
#include <cstdint>

#define S_LEN 8192
#define DIM   256
#define HID2  256
#define NTAG  16
#define NEGV  (-10000.0f)

typedef unsigned long long ull;

// ---------------- scratch (static __device__, per allocation rules) ----------
__device__ float g_pre[2u * S_LEN * 1024];        // 64 MB  [dir][t][m*4+gate]
__device__ float g_hs [S_LEN * 512];              // 16 MB  [t][dir*256+m]
__device__ float g_feats[S_LEN * NTAG];           // 512 KB [t][tag]
__device__ unsigned char g_back[S_LEN * NTAG];    // 128 KB backpointers

// ---------------- helpers ----------------------------------------------------
__device__ __forceinline__ void fma2(ull &d, ull a, ull b) {
    asm("fma.rn.f32x2 %0, %1, %2, %0;" : "+l"(d) : "l"(a), "l"(b));
}
__device__ __forceinline__ unsigned s2u(const void* p) {
    unsigned a;
    asm("{ .reg .u64 t; cvta.to.shared.u64 t, %1; cvt.u32.u64 %0, t; }"
        : "=r"(a) : "l"(p));
    return a;
}
__device__ __forceinline__ void remote_store(unsigned laddr, unsigned rank, float v) {
    unsigned r;
    asm volatile("mapa.shared::cluster.u32 %0, %1, %2;" : "=r"(r) : "r"(laddr), "r"(rank));
    asm volatile("st.shared::cluster.f32 [%0], %1;" :: "r"(r), "f"(v) : "memory");
}
__device__ __forceinline__ void cluster_sync_() {
    asm volatile("barrier.cluster.arrive.aligned;" ::: "memory");
    asm volatile("barrier.cluster.wait.aligned;"   ::: "memory");
}
__device__ __forceinline__ float sigm(float x) {
    return __fdividef(1.0f, 1.0f + __expf(-x));
}
__device__ __forceinline__ float tanh_(float x) {
    return __fdividef(2.0f, 1.0f + __expf(-2.0f * x)) - 1.0f;
}

// ============================================================================
// K1: embedding gather + input projections for both directions.
//   pre[dir][t][m*4+q] = b[q*256+m] + sum_d x_src[d] * w_ih[q*256+m][d]
//   dir==1 uses reversed x. Block: 16 timesteps x all 1024 gates, 256 threads.
// ============================================================================
__global__ __launch_bounds__(256) void k_pre(
    const int*   __restrict__ sent,  const float* __restrict__ emb,
    const float* __restrict__ w_ih_f, const float* __restrict__ b_f,
    const float* __restrict__ w_ih_b, const float* __restrict__ b_b)
{
    __shared__ float4 xs4[16 * 64];              // 16 timesteps x 256 floats
    const int dir = blockIdx.y;
    const int t0  = blockIdx.x * 16;
    const int tid = threadIdx.x;

    const float* w    = dir ? w_ih_b : w_ih_f;
    const float* bias = dir ? b_b    : b_f;

    {   // gather 16 embedding rows
        int r = tid >> 4, seg = tid & 15;
        int tg   = t0 + r;
        int tsrc = dir ? (S_LEN - 1 - tg) : tg;
        int tok  = __ldg(&sent[tsrc]);
        const float4* er = (const float4*)(emb + (size_t)tok * DIM);
#pragma unroll
        for (int ii = 0; ii < 4; ii++)
            xs4[r * 64 + seg + 16 * ii] = __ldg(&er[seg + 16 * ii]);
    }
    __syncthreads();

    const int m = tid;                            // hidden unit 0..255
    for (int q = 0; q < 4; q++) {                 // gate i,f,g,o
        const float4* wr = (const float4*)(w + (size_t)(q * HID2 + m) * DIM);
        float acc[16];
#pragma unroll
        for (int tt = 0; tt < 16; tt++) acc[tt] = 0.0f;
        for (int k4 = 0; k4 < 64; k4++) {
            float4 w4 = __ldg(&wr[k4]);
#pragma unroll
            for (int tt = 0; tt < 16; tt++) {
                float4 x4 = xs4[tt * 64 + k4];
                acc[tt] += w4.x * x4.x + w4.y * x4.y + w4.z * x4.z + w4.w * x4.w;
            }
        }
        float bq = __ldg(&bias[q * HID2 + m]);
        size_t base = ((size_t)dir * S_LEN + t0) * 1024 + (size_t)m * 4 + q;
#pragma unroll
        for (int tt = 0; tt < 16; tt++)
            g_pre[base + (size_t)tt * 1024] = acc[tt] + bq;
    }
}

// ============================================================================
// K2: bidirectional LSTM recurrence. 2 clusters of 8 CTAs (one per direction).
//   - W_hh entirely in registers (64 f32-pairs per thread)
//   - h double-buffered in per-CTA smem, broadcast via st.shared::cluster
//   - matvec via fma.rn.f32x2 (packed pairs)
// Thread map: warp w (0..7) owns 4 units; lane = u*8+s, unit m = rank*32+w*4+u,
//   s = k-slice (pairs k/2 = s + 8q, q=0..15).
// ============================================================================
__global__ void __cluster_dims__(8, 1, 1) __launch_bounds__(256, 1)
k_lstm(const float* __restrict__ w_hh_f, const float* __restrict__ w_hh_b,
       const float* __restrict__ h0_f,  const float* __restrict__ c0_f,
       const float* __restrict__ h0_b,  const float* __restrict__ c0_b)
{
    __shared__ float h_sm[2][HID2];
    const int tid  = threadIdx.x;
    const int rank = blockIdx.x & 7;
    const int dir  = blockIdx.x >> 3;
    const int w    = tid >> 5;
    const int lane = tid & 31;
    const int u    = lane >> 3;
    const int s    = lane & 7;
    const int m    = rank * 32 + w * 4 + u;

    const float* w_hh = dir ? w_hh_b : w_hh_f;
    const float* h0   = dir ? h0_b  : h0_f;
    const float* c0   = dir ? c0_b  : c0_f;

    // Load this thread's W_hh slice: 4 gates x 16 pairs (k = 2s+16q, +1)
    ull wv[4][16];
#pragma unroll
    for (int g = 0; g < 4; g++) {
        const ull* row = (const ull*)(w_hh + (size_t)(g * HID2 + m) * HID2);
#pragma unroll
        for (int q = 0; q < 16; q++)
            wv[g][q] = __ldg(&row[s + 8 * q]);
    }

    if (tid < HID2) h_sm[0][tid] = h0[tid];
    float c = c0[m];
    __syncthreads();
    cluster_sync_();

    const unsigned haddr0 = s2u(&h_sm[0][m]);
    const unsigned haddr1 = s2u(&h_sm[1][m]);

    const float4* prep = (const float4*)(g_pre + (size_t)dir * S_LEN * 1024) + m;
    float4 pre_cur = __ldg(&prep[0]);
    float* hs_out = g_hs + dir * HID2 + m;
    int p = 0;

    for (int t = 0; t < S_LEN; t++) {
        int tn = (t + 1 < S_LEN) ? t + 1 : t;
        float4 pre_next = __ldg(&prep[(size_t)tn * 256]);   // prefetch next step

        ull a0 = 0, a1 = 0, a2 = 0, a3 = 0;
        const ull* hp = (const ull*)&h_sm[p][0];
#pragma unroll
        for (int q = 0; q < 16; q++) {
            ull h2 = hp[s + 8 * q];
            fma2(a0, wv[0][q], h2);
            fma2(a1, wv[1][q], h2);
            fma2(a2, wv[2][q], h2);
            fma2(a3, wv[3][q], h2);
        }
        float2 f0 = *(float2*)&a0, f1 = *(float2*)&a1,
               f2 = *(float2*)&a2, f3 = *(float2*)&a3;
        float s0 = f0.x + f0.y, s1 = f1.x + f1.y,
              s2 = f2.x + f2.y, s3 = f3.x + f3.y;
#pragma unroll
        for (int msk = 1; msk < 8; msk <<= 1) {
            s0 += __shfl_xor_sync(0xffffffffu, s0, msk);
            s1 += __shfl_xor_sync(0xffffffffu, s1, msk);
            s2 += __shfl_xor_sync(0xffffffffu, s2, msk);
            s3 += __shfl_xor_sync(0xffffffffu, s3, msk);
        }
        float gi = sigm (pre_cur.x + s0);
        float gf = sigm (pre_cur.y + s1);
        float gg = tanh_(pre_cur.z + s2);
        float go = sigm (pre_cur.w + s3);
        c = gf * c + gi * gg;
        float h = go * tanh_(c);

        // broadcast h[m] to all 8 CTAs' next-phase buffer (lane s -> rank s)
        remote_store(p ? haddr0 : haddr1, (unsigned)s, h);
        if (s == 0) {
            int tpos = dir ? (S_LEN - 1 - t) : t;
            hs_out[(size_t)tpos * 512] = h;
        }
        cluster_sync_();          // release stores / acquire for next reads
        pre_cur = pre_next;
        p ^= 1;
    }
}

// ============================================================================
// K3: feats[t][tag] = b_out[tag] + sum_{k<512} hs[t][k] * w_out[tag][k]
// ============================================================================
__global__ __launch_bounds__(128) void k_feats(
    const float* __restrict__ w_out, const float* __restrict__ b_out)
{
    __shared__ float w_sm[NTAG * 516];            // padded rows (516 % 32 == 4)
    const int tid = threadIdx.x;
    for (int idx = tid; idx < NTAG * 512; idx += 128)
        w_sm[(idx >> 9) * 516 + (idx & 511)] = __ldg(&w_out[idx]);
    __syncthreads();

    const int tl  = tid >> 4;
    const int tag = tid & 15;
    const int t   = blockIdx.x * 8 + tl;
    const float4* hp = (const float4*)(g_hs + (size_t)t * 512);
    const float4* wp = (const float4*)(w_sm + tag * 516);
    float acc = 0.0f;
#pragma unroll 4
    for (int k4 = 0; k4 < 128; k4++) {
        float4 h4 = hp[k4];
        float4 w4 = wp[k4];
        acc += h4.x * w4.x + h4.y * w4.y + h4.z * w4.z + h4.w * w4.w;
    }
    g_feats[t * NTAG + tag] = acc + __ldg(&b_out[tag]);
}

// ============================================================================
// K4: Viterbi forward (1 warp, lane-per-tag) + backtrack.
//   Backpointers -> global (L2-resident); backtrack loads are address-
//   independent of the tag chain, so the serial chain is pure ALU.
// ============================================================================
__global__ __launch_bounds__(32) void k_vit(
    const float* __restrict__ trans, float* __restrict__ out, int out_size)
{
    __shared__ float fin_sm[NTAG];
    const int tid = threadIdx.x;
    const int j   = tid & 15;

    float tr[NTAG];
#pragma unroll
    for (int i = 0; i < NTAG; i++) tr[i] = __ldg(&trans[j * NTAG + i]);

    float score = (j == 0) ? 0.0f : NEGV;         // init: START=0 gets 0
    float fcur  = g_feats[j];                     // feats[0][j]

    for (int t = 0; t < S_LEN; t++) {
        float fnext = (t + 1 < S_LEN) ? g_feats[(t + 1) * NTAG + j] : 0.0f;
        float best = -3.4e38f; int bi = 0;
#pragma unroll
        for (int i = 0; i < NTAG; i++) {
            float si = __shfl_sync(0xffffffffu, score, i);
            float cand = si + tr[i];
            if (cand > best) { best = cand; bi = i; }   // first-max (strict >)
        }
        if (tid < NTAG) g_back[t * NTAG + j] = (unsigned char)bi;
        score = best + fcur;
        fcur  = fnext;
    }

    if (tid < NTAG) fin_sm[j] = score + __ldg(&trans[1 * NTAG + j]); // + trans[END]
    __syncwarp();

    if (tid == 0) {
        float bs = fin_sm[0]; int bl = 0;
#pragma unroll
        for (int i = 1; i < NTAG; i++)
            if (fin_sm[i] > bs) { bs = fin_sm[i]; bl = i; }

        const int off = (out_size > S_LEN) ? 1 : 0;
        if (off) out[0] = bs;

        int tag = bl;
#pragma unroll 4
        for (int t = S_LEN - 1; t > 0; t--) {
            out[off + t] = (float)tag;
            uint4 row = *(const uint4*)&g_back[t * NTAG];   // 16 backptrs, addr indep of tag
            unsigned wsel = (tag & 8) ? ((tag & 4) ? row.w : row.z)
                                      : ((tag & 4) ? row.y : row.x);
            tag = (int)((wsel >> (8 * (tag & 3))) & 0xFu);
        }
        out[off] = (float)tag;
    }
}

// ============================================================================
extern "C" void kernel_launch(void* const* d_in, const int* in_sizes, int n_in,
                              void* d_out, int out_size)
{
    (void)in_sizes; (void)n_in;
    const int*   sent   = (const int*)  d_in[0];
    const float* emb    = (const float*)d_in[1];
    const float* w_ih_f = (const float*)d_in[2];
    const float* w_hh_f = (const float*)d_in[3];
    const float* b_f    = (const float*)d_in[4];
    const float* w_ih_b = (const float*)d_in[5];
    const float* w_hh_b = (const float*)d_in[6];
    const float* b_b    = (const float*)d_in[7];
    const float* h0_f   = (const float*)d_in[8];
    const float* c0_f   = (const float*)d_in[9];
    const float* h0_b   = (const float*)d_in[10];
    const float* c0_b   = (const float*)d_in[11];
    const float* w_out  = (const float*)d_in[12];
    const float* b_out  = (const float*)d_in[13];
    const float* trans  = (const float*)d_in[14];

    k_pre  <<<dim3(512, 2), 256>>>(sent, emb, w_ih_f, b_f, w_ih_b, b_b);
    k_lstm <<<16, 256>>>(w_hh_f, w_hh_b, h0_f, c0_f, h0_b, c0_b);
    k_feats<<<1024, 128>>>(w_out, b_out);
    k_vit  <<<1, 32>>>(trans, (float*)d_out, out_size);
}

// round 6
// speedup vs baseline: 1.0750x; 1.0750x over previous
#include <cuda_runtime.h>
#include <cstdint>

#define S_LEN 8192
#define DIM   256
#define HID2  256
#define NTAG  16
#define NEGV  (-10000.0f)
typedef unsigned long long ull;

__device__ float g_pre[2u * S_LEN * 1024];
__device__ float g_hs [S_LEN * 512];
__device__ float g_feats[S_LEN * NTAG];
__device__ unsigned char g_back[S_LEN * NTAG];

__device__ __forceinline__ void fma2(ull &d, ull a, ull b) {
    asm("fma.rn.f32x2 %0, %1, %2, %0;" : "+l"(d) : "l"(a), "l"(b));
}
__device__ __forceinline__ unsigned s2u(const void* p) {
    unsigned a;
    asm("{ .reg .u64 t; cvta.to.shared.u64 t, %1; cvt.u32.u64 %0, t; }" : "=r"(a) : "l"(p));
    return a;
}
__device__ __forceinline__ unsigned mapa_(unsigned la, unsigned rk) {
    unsigned r;
    asm("mapa.shared::cluster.u32 %0, %1, %2;" : "=r"(r) : "r"(la), "r"(rk));
    return r;
}
__device__ __forceinline__ void cluster_sync_() {
    asm volatile("barrier.cluster.arrive.aligned;" ::: "memory");
    asm volatile("barrier.cluster.wait.aligned;"   ::: "memory");
}
__device__ __forceinline__ float sigm(float x) { return __fdividef(1.0f, 1.0f + __expf(-x)); }
__device__ __forceinline__ float tanh_(float x) { return __fdividef(2.0f, 1.0f + __expf(-2.0f * x)) - 1.0f; }

#define WAIT_ACQ(maddr, par) do {                                             \
    asm volatile("{\n\t.reg .pred P;\n\tWL_%=:\n\t"                           \
        "mbarrier.try_wait.parity.acquire.cluster.shared::cta.b64 P, [%0], %1, 0x989680;\n\t" \
        "@P bra WD_%=;\n\tbra WL_%=;\n\tWD_%=:\n\t}"                          \
        :: "r"(maddr), "r"(par) : "memory");                                  \
} while (0)

// ========================= K1: input projections ============================
__global__ __launch_bounds__(256) void k_pre(
    const int* __restrict__ sent, const float* __restrict__ emb,
    const float* __restrict__ w_ih_f, const float* __restrict__ b_f,
    const float* __restrict__ w_ih_b, const float* __restrict__ b_b)
{
    __shared__ float4 xs4[16 * 64];
    const int dir = blockIdx.y, t0 = blockIdx.x * 16, tid = threadIdx.x;
    const float* w    = dir ? w_ih_b : w_ih_f;
    const float* bias = dir ? b_b    : b_f;
    {
        int r = tid >> 4, seg = tid & 15;
        int tsrc = dir ? (S_LEN - 1 - (t0 + r)) : (t0 + r);
        int tok  = __ldg(&sent[tsrc]);
        const float4* er = (const float4*)(emb + (size_t)tok * DIM);
#pragma unroll
        for (int ii = 0; ii < 4; ii++) xs4[r * 64 + seg + 16 * ii] = __ldg(&er[seg + 16 * ii]);
    }
    __syncthreads();
    const int m = tid;
    for (int q = 0; q < 4; q++) {
        const float4* wr = (const float4*)(w + (size_t)(q * HID2 + m) * DIM);
        float acc[16];
#pragma unroll
        for (int tt = 0; tt < 16; tt++) acc[tt] = 0.0f;
        for (int k4 = 0; k4 < 64; k4++) {
            float4 w4 = __ldg(&wr[k4]);
#pragma unroll
            for (int tt = 0; tt < 16; tt++) {
                float4 x4 = xs4[tt * 64 + k4];
                acc[tt] += w4.x * x4.x + w4.y * x4.y + w4.z * x4.z + w4.w * x4.w;
            }
        }
        float bq = __ldg(&bias[q * HID2 + m]);
        size_t base = ((size_t)dir * S_LEN + t0) * 1024 + (size_t)m * 4 + q;
#pragma unroll
        for (int tt = 0; tt < 16; tt++) g_pre[base + (size_t)tt * 1024] = acc[tt] + bq;
    }
}

// ===== K2: LSTM recurrence, 8-CTA cluster/dir, mbarrier triple-buffer =======
__global__ void __cluster_dims__(8, 1, 1) __launch_bounds__(256, 1)
k_lstm(const float* __restrict__ w_hh_f, const float* __restrict__ w_hh_b,
       const float* __restrict__ h0_f, const float* __restrict__ c0_f,
       const float* __restrict__ h0_b, const float* __restrict__ c0_b)
{
    __shared__ float h_sm[3][HID2];
    __shared__ ull mb[3];
    const int tid  = threadIdx.x;
    const int rank = blockIdx.x & 7, dir = blockIdx.x >> 3;
    const int w = tid >> 5, lane = tid & 31, u = lane >> 3, s = lane & 7;
    const int m = rank * 32 + w * 4 + u;

    const float* w_hh = dir ? w_hh_b : w_hh_f;
    const float* h0   = dir ? h0_b : h0_f;
    const float* c0   = dir ? c0_b : c0_f;

    ull wv[4][16];
#pragma unroll
    for (int g = 0; g < 4; g++) {
        const ull* row = (const ull*)(w_hh + (size_t)(g * HID2 + m) * HID2);
#pragma unroll
        for (int q = 0; q < 16; q++) wv[g][q] = __ldg(&row[s + 8 * q]);
    }

    if (tid < 3) {
        unsigned ma = s2u(&mb[tid]);
        asm volatile("mbarrier.init.shared.b64 [%0], 64;" :: "r"(ma) : "memory");
    }
    if (tid < HID2) h_sm[0][tid] = h0[tid];
    float c = c0[m];
    __syncthreads();
    cluster_sync_();

    unsigned mba[3]  = { s2u(&mb[0]), s2u(&mb[1]), s2u(&mb[2]) };
    unsigned dsta[3] = { s2u(&h_sm[0][rank * 32 + w * 4]),
                         s2u(&h_sm[1][rank * 32 + w * 4]),
                         s2u(&h_sm[2][rank * 32 + w * 4]) };

    const float4* prep = (const float4*)(g_pre + (size_t)dir * S_LEN * 1024) + m;
    float4 pre_cur = __ldg(&prep[0]);
    float* hs_out = g_hs + dir * HID2 + m;

    auto STEP = [&](int t, int b, int dowait, int parity) {
        int tn = (t + 1 < S_LEN) ? t + 1 : t;
        float4 pre_next = __ldg(&prep[(size_t)tn * 256]);
        if (dowait) WAIT_ACQ(mba[b], parity);
        ull a0 = 0, a1 = 0, a2 = 0, a3 = 0;
        const ull* hp = (const ull*)&h_sm[b][0];
#pragma unroll
        for (int q = 0; q < 16; q++) {
            ull h2 = hp[s + 8 * q];
            fma2(a0, wv[0][q], h2); fma2(a1, wv[1][q], h2);
            fma2(a2, wv[2][q], h2); fma2(a3, wv[3][q], h2);
        }
        float2 f0 = *(float2*)&a0, f1 = *(float2*)&a1, f2 = *(float2*)&a2, f3 = *(float2*)&a3;
        float s0 = f0.x + f0.y, s1 = f1.x + f1.y, s2 = f2.x + f2.y, s3 = f3.x + f3.y;
#pragma unroll
        for (int msk = 1; msk < 8; msk <<= 1) {
            s0 += __shfl_xor_sync(0xffffffffu, s0, msk);
            s1 += __shfl_xor_sync(0xffffffffu, s1, msk);
            s2 += __shfl_xor_sync(0xffffffffu, s2, msk);
            s3 += __shfl_xor_sync(0xffffffffu, s3, msk);
        }
        float gi = sigm(pre_cur.x + s0), gf = sigm(pre_cur.y + s1);
        float gg = tanh_(pre_cur.z + s2), go = sigm(pre_cur.w + s3);
        c = gf * c + gi * gg;
        float h = go * tanh_(c);

        int bn = (b + 1) % 3;
        float p0 = __shfl_sync(0xffffffffu, h, s);
        float p1 = __shfl_sync(0xffffffffu, h, s + 8);
        float p2 = __shfl_sync(0xffffffffu, h, s + 16);
        float p3 = __shfl_sync(0xffffffffu, h, s + 24);
        if (lane < 8) {
            unsigned da = mapa_(dsta[bn], (unsigned)lane);
            asm volatile("st.shared::cluster.v4.f32 [%0], {%1,%2,%3,%4};"
                         :: "r"(da), "f"(p0), "f"(p1), "f"(p2), "f"(p3) : "memory");
            unsigned ba = mapa_(mba[bn], (unsigned)lane);
            asm volatile("mbarrier.arrive.release.cluster.shared::cluster.b64 _, [%0];"
                         :: "r"(ba) : "memory");
        }
        if (s == 0) {
            int tpos = dir ? (S_LEN - 1 - t) : t;
            hs_out[(size_t)tpos * 512] = h;
        }
        pre_cur = pre_next;
    };

    STEP(0, 0, 0, 0);
    int par = 0;
    for (int t = 1; t < S_LEN - 1; t += 3) {
        STEP(t,     1, 1, par);
        STEP(t + 1, 2, 1, par);
        STEP(t + 2, 0, 1, par);
        par ^= 1;
    }
    STEP(S_LEN - 1, 1, 1, par);
    cluster_sync_();
}

// ========================= K3: output projection ============================
__global__ __launch_bounds__(128) void k_feats(
    const float* __restrict__ w_out, const float* __restrict__ b_out)
{
    __shared__ float w_sm[NTAG * 516];
    const int tid = threadIdx.x;
    for (int idx = tid; idx < NTAG * 512; idx += 128)
        w_sm[(idx >> 9) * 516 + (idx & 511)] = __ldg(&w_out[idx]);
    __syncthreads();
    const int tl = tid >> 4, tag = tid & 15;
    const int t = blockIdx.x * 8 + tl;
    const float4* hp = (const float4*)(g_hs + (size_t)t * 512);
    const float4* wp = (const float4*)(w_sm + tag * 516);
    float acc = 0.0f;
#pragma unroll 4
    for (int k4 = 0; k4 < 128; k4++) {
        float4 h4 = hp[k4], w4 = wp[k4];
        acc += h4.x * w4.x + h4.y * w4.y + h4.z * w4.z + h4.w * w4.w;
    }
    g_feats[t * NTAG + tag] = acc + __ldg(&b_out[tag]);
}

// ========================= K4: Viterbi ======================================
__global__ __launch_bounds__(32) void k_vit(
    const float* __restrict__ trans, float* __restrict__ out, int out_size)
{
    __shared__ float fin_sm[NTAG];
    const int tid = threadIdx.x, j = tid & 15;
    float tr[NTAG];
#pragma unroll
    for (int i = 0; i < NTAG; i++) tr[i] = __ldg(&trans[j * NTAG + i]);

    float score = (j == 0) ? 0.0f : NEGV;
    float fcur = g_feats[j];
    for (int t = 0; t < S_LEN; t++) {
        float fnext = (t + 1 < S_LEN) ? g_feats[(t + 1) * NTAG + j] : 0.0f;
        float best = -3.4e38f; int bi = 0;
#pragma unroll
        for (int i = 0; i < NTAG; i++) {
            float si = __shfl_sync(0xffffffffu, score, i);
            float cand = si + tr[i];
            if (cand > best) { best = cand; bi = i; }
        }
        if (tid < NTAG) g_back[t * NTAG + j] = (unsigned char)bi;
        score = best + fcur;
        fcur = fnext;
    }
    if (tid < NTAG) fin_sm[j] = score + __ldg(&trans[1 * NTAG + j]);
    __syncwarp();
    if (tid == 0) {
        float bs = fin_sm[0]; int bl = 0;
#pragma unroll
        for (int i = 1; i < NTAG; i++) if (fin_sm[i] > bs) { bs = fin_sm[i]; bl = i; }
        const int off = (out_size > S_LEN) ? 1 : 0;
        if (off) out[0] = bs;
        int tag = bl;
#pragma unroll 4
        for (int t = S_LEN - 1; t > 0; t--) {
            out[off + t] = (float)tag;
            uint4 row = *(const uint4*)&g_back[t * NTAG];
            unsigned wsel = (tag & 8) ? ((tag & 4) ? row.w : row.z)
                                      : ((tag & 4) ? row.y : row.x);
            tag = (int)((wsel >> (8 * (tag & 3))) & 0xFu);
        }
        out[off] = (float)tag;
    }
}

extern "C" void kernel_launch(void* const* d_in, const int* in_sizes, int n_in,
                              void* d_out, int out_size)
{
    (void)in_sizes; (void)n_in;
    const int*   sent   = (const int*)  d_in[0];
    const float* emb    = (const float*)d_in[1];
    const float* w_ih_f = (const float*)d_in[2];
    const float* w_hh_f = (const float*)d_in[3];
    const float* b_f    = (const float*)d_in[4];
    const float* w_ih_b = (const float*)d_in[5];
    const float* w_hh_b = (const float*)d_in[6];
    const float* b_b    = (const float*)d_in[7];
    const float* h0_f   = (const float*)d_in[8];
    const float* c0_f   = (const float*)d_in[9];
    const float* h0_b   = (const float*)d_in[10];
    const float* c0_b   = (const float*)d_in[11];
    const float* w_out  = (const float*)d_in[12];
    const float* b_out  = (const float*)d_in[13];
    const float* trans  = (const float*)d_in[14];

    k_pre  <<<dim3(512, 2), 256>>>(sent, emb, w_ih_f, b_f, w_ih_b, b_b);
    k_lstm <<<16, 256>>>(w_hh_f, w_hh_b, h0_f, c0_f, h0_b, c0_b);
    k_feats<<<1024, 128>>>(w_out, b_out);
    k_vit  <<<1, 32>>>(trans, (float*)d_out, out_size);
}